// round 4
// baseline (speedup 1.0000x reference)
#include <cuda_runtime.h>

#define FULL_MASK 0xffffffffu

// Amplitude index layout: i = k*32 + lane  (k = register slot 0..15, lane 0..31)
//   bits 0..4  = lane   -> qubits 8..4  (qubit w <-> bit 8-w)
//   bits 5..8  = k bits -> qubits 3..0
// Shared permute buffer swizzle: phys = i ^ k  (keeps gather conflict-free)
__device__ __forceinline__ int swz(int i) { return i ^ ((i >> 5) & 15); }

// Gate on a register bit RB (index bit 5+RB, qubit 3-RB).
// m10 = -conj(m01), m11 = conj(m00).
template <int RB>
__device__ __forceinline__ void apply_reg(float (&re)[16], float (&im)[16],
                                          float2 m00, float2 m01) {
    const int d = 1 << RB;
#pragma unroll
    for (int t = 0; t < 8; t++) {
        const int k = ((t >> RB) << (RB + 1)) | (t & (d - 1));
        const int j = k | d;
        float ar = re[k], ai = im[k], br = re[j], bi = im[j];
        re[k] =  m00.x * ar - m00.y * ai + m01.x * br - m01.y * bi;
        im[k] =  m00.x * ai + m00.y * ar + m01.x * bi + m01.y * br;
        re[j] = -m01.x * ar - m01.y * ai + m00.x * br + m00.y * bi;
        im[j] = -m01.x * ai + m01.y * ar + m00.x * bi - m00.y * br;
    }
}

// Gate on a lane bit P (index bit P, qubit 8-P). Butterfly via shfl_xor:
// each lane computes only its own new amplitude with sign-selected coeffs.
template <int P>
__device__ __forceinline__ void apply_cross(float (&re)[16], float (&im)[16],
                                            float2 m00, float2 m01, int lane) {
    const int msk = 1 << P;
    const bool hi = (lane & msk) != 0;
    const float cmr = m00.x;
    const float cmi = hi ? -m00.y : m00.y;
    const float cpr = hi ? -m01.x : m01.x;
    const float cpi = m01.y;
#pragma unroll
    for (int k = 0; k < 16; k++) {
        float pr = __shfl_xor_sync(FULL_MASK, re[k], msk);
        float pi = __shfl_xor_sync(FULL_MASK, im[k], msk);
        float mr = re[k], mi = im[k];
        re[k] = cmr * mr - cmi * mi + cpr * pr - cpi * pi;
        im[k] = cmr * mi + cmi * mr + cpr * pi + cpi * pr;
    }
}

__global__ void __launch_bounds__(256)
qsim_kernel(const float* __restrict__ x, const float* __restrict__ wt,
            float* __restrict__ out, int B) {
    __shared__ float2 s_m00[27];
    __shared__ float2 s_m01[27];
    __shared__ unsigned short s_perm[3 * 512];
    __shared__ float2 s_buf[8][512];

    const int tid = threadIdx.x;

    // ---- per-block setup: 27 rotation matrices (m00, m01; m10/m11 derived) ----
    if (tid < 27) {
        const float* p = wt + tid * 3;           // (l*9 + w)*3
        float phi = p[0], th = p[1], om = p[2];
        float a  = 0.5f * (phi + om);
        float bb = 0.5f * (phi - om);
        float c = cosf(0.5f * th), s = sinf(0.5f * th);
        float ca = cosf(a),  sa = sinf(a);
        float cb = cosf(bb), sb = sinf(bb);
        s_m00[tid] = make_float2(c * ca, -c * sa);   // e^{-i a} c
        s_m01[tid] = make_float2(-s * cb, -s * sb);  // -e^{i b} s
    }
    // ---- per-block setup: CNOT-ring permutations (basis-index maps) ----
    for (int i = tid; i < 3 * 512; i += blockDim.x) {
        int l = i >> 9, idx = i & 511, r = l + 1;
        int v = idx;
#pragma unroll
        for (int g = 0; g < 9; g++) {
            int pc = 8 - g;
            int t = g + r; if (t >= 9) t -= 9;
            int pt = 8 - t;
            v ^= ((v >> pc) & 1) << pt;
        }
        s_perm[i] = (unsigned short)v;
    }
    __syncthreads();

    const int lane = tid & 31;
    const int warp = tid >> 5;
    float2* buf = s_buf[warp];
    const int gw = blockIdx.x * (blockDim.x >> 5) + warp;
    const int nw = gridDim.x * (blockDim.x >> 5);

    for (int b = gw; b < B; b += nw) {
        // ---- initial separable state ----
        float cs[9], sn[9];
#pragma unroll
        for (int w = 0; w < 9; w++) {
            float h = 0.5f * __ldg(&x[b * 9 + w]);
            __sincosf(h, &sn[w], &cs[w]);
        }
        float re[16], im[16];
        float lf = 1.0f;
#pragma unroll
        for (int p = 0; p < 5; p++)
            lf *= ((lane >> p) & 1) ? sn[8 - p] : cs[8 - p];
        const int lpc = __popc(lane);
#pragma unroll
        for (int k = 0; k < 16; k++) {
            float f = lf;
#pragma unroll
            for (int p = 0; p < 4; p++)
                f *= ((k >> p) & 1) ? sn[3 - p] : cs[3 - p];
            int pc = (lpc + __popc(k)) & 3;     // phase (-i)^popcount
            float g = (pc & 2) ? -f : f;
            re[k] = (pc & 1) ? 0.0f : g;
            im[k] = (pc & 1) ? -g : 0.0f;
        }

        // ---- 3 layers: 9 rotations + CNOT-ring permutation ----
        for (int l = 0; l < 3; l++) {
            const int base = l * 9;
            apply_reg<3>(re, im, s_m00[base + 0], s_m01[base + 0]);   // qubit 0, bit 8
            apply_reg<2>(re, im, s_m00[base + 1], s_m01[base + 1]);
            apply_reg<1>(re, im, s_m00[base + 2], s_m01[base + 2]);
            apply_reg<0>(re, im, s_m00[base + 3], s_m01[base + 3]);   // qubit 3, bit 5
            apply_cross<4>(re, im, s_m00[base + 4], s_m01[base + 4], lane);
            apply_cross<3>(re, im, s_m00[base + 5], s_m01[base + 5], lane);
            apply_cross<2>(re, im, s_m00[base + 6], s_m01[base + 6], lane);
            apply_cross<1>(re, im, s_m00[base + 7], s_m01[base + 7], lane);
            apply_cross<0>(re, im, s_m00[base + 8], s_m01[base + 8], lane);

            const unsigned short* pm = s_perm + (l << 9);
            __syncwarp();
#pragma unroll
            for (int k = 0; k < 16; k++) {
                int i = k * 32 + lane;
                buf[swz((int)pm[i])] = make_float2(re[k], im[k]);
            }
            __syncwarp();
#pragma unroll
            for (int k = 0; k < 16; k++) {
                float2 v = buf[swz(k * 32 + lane)];
                re[k] = v.x; im[k] = v.y;
            }
        }

        // ---- measurement: <Z_w> for w = 0..8 ----
        float pr[16];
#pragma unroll
        for (int k = 0; k < 16; k++) pr[k] = re[k] * re[k] + im[k] * im[k];

        float acc[9];
#pragma unroll
        for (int w = 0; w < 4; w++) {           // Z bit lives in k-bits
            float s = 0.0f;
#pragma unroll
            for (int k = 0; k < 16; k++)
                s += ((k >> (3 - w)) & 1) ? -pr[k] : pr[k];
            acc[w] = s;
        }
        float T = 0.0f;
#pragma unroll
        for (int k = 0; k < 16; k++) T += pr[k];
#pragma unroll
        for (int w = 4; w < 9; w++)             // Z bit lives in lane bits
            acc[w] = ((lane >> (8 - w)) & 1) ? -T : T;

#pragma unroll
        for (int off = 16; off > 0; off >>= 1) {
#pragma unroll
            for (int w = 0; w < 9; w++)
                acc[w] += __shfl_xor_sync(FULL_MASK, acc[w], off);
        }
        if (lane == 0) {
#pragma unroll
            for (int w = 0; w < 9; w++) out[b * 9 + w] = acc[w];
        }
    }
}

extern "C" void kernel_launch(void* const* d_in, const int* in_sizes, int n_in,
                              void* d_out, int out_size) {
    const float* x  = (const float*)d_in[0];   // (32768, 9) fp32
    const float* wt = (const float*)d_in[1];   // (3, 9, 3) fp32
    float* out = (float*)d_out;                // (32768, 9) fp32
    int B = in_sizes[0] / 9;
    qsim_kernel<<<2048, 256>>>(x, wt, out, B);
}

// round 6
// speedup vs baseline: 1.0849x; 1.0849x over previous
#include <cuda_runtime.h>

#define FULL_MASK 0xffffffffu
typedef unsigned long long u64;

// ---- f32x2 packed helpers (sm_103a FFMA2 only reachable via PTX) ----
__device__ __forceinline__ u64 pk(float lo, float hi) {
    u64 r; asm("mov.b64 %0,{%1,%2};" : "=l"(r) : "f"(lo), "f"(hi)); return r;
}
__device__ __forceinline__ void up(u64 v, float& lo, float& hi) {
    asm("mov.b64 {%0,%1},%2;" : "=f"(lo), "=f"(hi) : "l"(v));
}
__device__ __forceinline__ u64 f2fma(u64 a, u64 b, u64 c) {
    u64 d; asm("fma.rn.f32x2 %0,%1,%2,%3;" : "=l"(d) : "l"(a), "l"(b), "l"(c)); return d;
}
__device__ __forceinline__ u64 f2mul(u64 a, u64 b) {
    u64 d; asm("mul.rn.f32x2 %0,%1,%2;" : "=l"(d) : "l"(a), "l"(b)); return d;
}
__device__ __forceinline__ u64 swp(u64 v) {
    float a, b; up(v, a, b); return pk(b, a);
}

// Amplitude index layout: i = k*32 + lane.
//   lane bits 0..4 -> qubits 8..4 ; k bits 0..3 -> qubits 3..0
// Packed: R[p]/I[p] hold k=2p (lo half) and k=2p+1 (hi half).
__device__ __forceinline__ int swz(int i) { return i ^ ((i >> 5) & 15); }

// Gate on k-bit (PB+1), PB in {0,1,2}: butterfly across packs, broadcast coeffs.
template <int PB>
__device__ __forceinline__ void gate_reg(u64 (&R)[8], u64 (&I)[8],
                                         float2 m00, float2 m01) {
    const u64 c00x = pk(m00.x, m00.x), c00y = pk(m00.y, m00.y);
    const u64 c01x = pk(m01.x, m01.x), c01y = pk(m01.y, m01.y);
    const u64 n00y = pk(-m00.y, -m00.y), n01x = pk(-m01.x, -m01.x);
    const u64 n01y = pk(-m01.y, -m01.y);
    const int d = 1 << PB;
#pragma unroll
    for (int t = 0; t < 4; t++) {
        const int q = ((t >> PB) << (PB + 1)) | (t & (d - 1));
        const int j = q | d;
        u64 A = R[q], Ai = I[q], Bv = R[j], Bi = I[j];
        R[q] = f2fma(c00x, A,  f2fma(n00y, Ai, f2fma(c01x, Bv, f2mul(n01y, Bi))));
        I[q] = f2fma(c00x, Ai, f2fma(c00y, A,  f2fma(c01x, Bi, f2mul(c01y, Bv))));
        R[j] = f2fma(n01x, A,  f2fma(n01y, Ai, f2fma(c00x, Bv, f2mul(c00y, Bi))));
        I[j] = f2fma(n01x, Ai, f2fma(c01y, A,  f2fma(c00x, Bi, f2mul(n00y, Bv))));
    }
}

// Gate on k-bit 0: butterfly within each pack (lo=k, hi=k|1).
__device__ __forceinline__ void gate_reg0(u64 (&R)[8], u64 (&I)[8],
                                          float2 m00, float2 m01) {
    const u64 c00x = pk(m00.x, m00.x);
    const u64 cA = pk(-m00.y,  m00.y);   // on I  for R'
    const u64 cB = pk( m00.y, -m00.y);   // on R  for I'
    const u64 cC = pk( m01.x, -m01.x);   // on swapR for R', swapI for I'
    const u64 cD = pk(-m01.y, -m01.y);   // on swapI for R'
    const u64 cE = pk( m01.y,  m01.y);   // on swapR for I'
#pragma unroll
    for (int p = 0; p < 8; p++) {
        u64 sR = swp(R[p]), sI = swp(I[p]);
        u64 Rn = f2fma(c00x, R[p], f2fma(cA, I[p], f2fma(cC, sR, f2mul(cD, sI))));
        u64 In = f2fma(c00x, I[p], f2fma(cB, R[p], f2fma(cC, sI, f2mul(cE, sR))));
        R[p] = Rn; I[p] = In;
    }
}

// Gate on lane bit P (qubit 8-P): shfl butterfly, per-lane scalar coeffs
// broadcast to both pack halves.
template <int P>
__device__ __forceinline__ void gate_cross(u64 (&R)[8], u64 (&I)[8],
                                           float2 m00, float2 m01, int lane) {
    const int msk = 1 << P;
    const bool hi = (lane & msk) != 0;
    const float cmr = m00.x;
    const float cmi = hi ? -m00.y : m00.y;
    const float cpr = hi ? -m01.x : m01.x;
    const float cpi = m01.y;
    const u64 kmr = pk(cmr, cmr), kmi = pk(cmi, cmi), nmi = pk(-cmi, -cmi);
    const u64 kpr = pk(cpr, cpr), kpi = pk(cpi, cpi), npi = pk(-cpi, -cpi);
#pragma unroll
    for (int p = 0; p < 8; p++) {
        u64 shR = __shfl_xor_sync(FULL_MASK, R[p], msk);
        u64 shI = __shfl_xor_sync(FULL_MASK, I[p], msk);
        u64 Rn = f2fma(kmr, R[p], f2fma(nmi, I[p], f2fma(kpr, shR, f2mul(npi, shI))));
        u64 In = f2fma(kmr, I[p], f2fma(kmi, R[p], f2fma(kpr, shI, f2mul(kpi, shR))));
        R[p] = Rn; I[p] = In;
    }
}

__global__ void __launch_bounds__(256)
qsim_kernel(const float* __restrict__ x, const float* __restrict__ wt,
            float* __restrict__ out, int B) {
    __shared__ float2 s_m00[27];
    __shared__ float2 s_m01[27];
    __shared__ unsigned short s_perm[3 * 512];
    __shared__ float2 s_buf[8][512];

    const int tid = threadIdx.x;

    // ---- per-block setup: 27 rotation matrices (m00, m01; m10/m11 derived) ----
    if (tid < 27) {
        const float* p = wt + tid * 3;           // (l*9 + w)*3
        float phi = p[0], th = p[1], om = p[2];
        float a  = 0.5f * (phi + om);
        float bb = 0.5f * (phi - om);
        float c = cosf(0.5f * th), s = sinf(0.5f * th);
        float ca = cosf(a),  sa = sinf(a);
        float cb = cosf(bb), sb = sinf(bb);
        s_m00[tid] = make_float2(c * ca, -c * sa);   // e^{-i a} c
        s_m01[tid] = make_float2(-s * cb, -s * sb);  // -e^{i b} s
    }
    // ---- per-block setup: CNOT-ring permutations (basis-index maps) ----
    for (int i = tid; i < 3 * 512; i += blockDim.x) {
        int l = i >> 9, idx = i & 511, r = l + 1;
        int v = idx;
#pragma unroll
        for (int g = 0; g < 9; g++) {
            int pc = 8 - g;
            int t = g + r; if (t >= 9) t -= 9;
            int pt = 8 - t;
            v ^= ((v >> pc) & 1) << pt;
        }
        s_perm[i] = (unsigned short)v;
    }
    __syncthreads();

    const int lane = tid & 31;
    const int warp = tid >> 5;
    float2* buf = s_buf[warp];
    const int gw = blockIdx.x * (blockDim.x >> 5) + warp;
    const int nw = gridDim.x * (blockDim.x >> 5);

    for (int b = gw; b < B; b += nw) {
        // ---- initial separable state (scalar, then pack) ----
        float cs[9], sn[9];
#pragma unroll
        for (int w = 0; w < 9; w++) {
            float h = 0.5f * __ldg(&x[b * 9 + w]);
            __sincosf(h, &sn[w], &cs[w]);
        }
        float lf = 1.0f;
#pragma unroll
        for (int p = 0; p < 5; p++)
            lf *= ((lane >> p) & 1) ? sn[8 - p] : cs[8 - p];
        const int lpc = __popc(lane);

        u64 R[8], I[8];
#pragma unroll
        for (int p = 0; p < 8; p++) {
            float rr[2], ii[2];
#pragma unroll
            for (int h = 0; h < 2; h++) {
                int k = 2 * p + h;
                float f = lf;
#pragma unroll
                for (int q = 0; q < 4; q++)
                    f *= ((k >> q) & 1) ? sn[3 - q] : cs[3 - q];
                int pc = (lpc + __popc(k)) & 3;     // phase (-i)^popcount
                float g = (pc & 2) ? -f : f;
                rr[h] = (pc & 1) ? 0.0f : g;
                ii[h] = (pc & 1) ? -g : 0.0f;
            }
            R[p] = pk(rr[0], rr[1]);
            I[p] = pk(ii[0], ii[1]);
        }

        // ---- 3 layers: 9 rotations + CNOT-ring permutation ----
        for (int l = 0; l < 3; l++) {
            const int base = l * 9;
            gate_reg<2>(R, I, s_m00[base + 0], s_m01[base + 0]);   // qubit 0 (k-bit 3)
            gate_reg<1>(R, I, s_m00[base + 1], s_m01[base + 1]);   // qubit 1 (k-bit 2)
            gate_reg<0>(R, I, s_m00[base + 2], s_m01[base + 2]);   // qubit 2 (k-bit 1)
            gate_reg0  (R, I, s_m00[base + 3], s_m01[base + 3]);   // qubit 3 (k-bit 0)
            gate_cross<4>(R, I, s_m00[base + 4], s_m01[base + 4], lane);
            gate_cross<3>(R, I, s_m00[base + 5], s_m01[base + 5], lane);
            gate_cross<2>(R, I, s_m00[base + 6], s_m01[base + 6], lane);
            gate_cross<1>(R, I, s_m00[base + 7], s_m01[base + 7], lane);
            gate_cross<0>(R, I, s_m00[base + 8], s_m01[base + 8], lane);

            const unsigned short* pm = s_perm + (l << 9);
            __syncwarp();
#pragma unroll
            for (int p = 0; p < 8; p++) {
                float r0, r1, i0, i1;
                up(R[p], r0, r1); up(I[p], i0, i1);
                buf[swz((int)pm[(2 * p) * 32 + lane])]     = make_float2(r0, i0);
                buf[swz((int)pm[(2 * p + 1) * 32 + lane])] = make_float2(r1, i1);
            }
            __syncwarp();
#pragma unroll
            for (int p = 0; p < 8; p++) {
                float2 a  = buf[swz((2 * p) * 32 + lane)];
                float2 bv = buf[swz((2 * p + 1) * 32 + lane)];
                R[p] = pk(a.x, bv.x);
                I[p] = pk(a.y, bv.y);
            }
        }

        // ---- measurement: <Z_w> for w = 0..8 ----
        float pr[16];
#pragma unroll
        for (int p = 0; p < 8; p++) {
            u64 P2 = f2fma(R[p], R[p], f2mul(I[p], I[p]));
            up(P2, pr[2 * p], pr[2 * p + 1]);
        }

        float acc[9];
#pragma unroll
        for (int w = 0; w < 4; w++) {           // Z bit lives in k-bits
            float s = 0.0f;
#pragma unroll
            for (int k = 0; k < 16; k++)
                s += ((k >> (3 - w)) & 1) ? -pr[k] : pr[k];
            acc[w] = s;
        }
        float T = 0.0f;
#pragma unroll
        for (int k = 0; k < 16; k++) T += pr[k];
#pragma unroll
        for (int w = 4; w < 9; w++)             // Z bit lives in lane bits
            acc[w] = ((lane >> (8 - w)) & 1) ? -T : T;

#pragma unroll
        for (int off = 16; off > 0; off >>= 1) {
#pragma unroll
            for (int w = 0; w < 9; w++)
                acc[w] += __shfl_xor_sync(FULL_MASK, acc[w], off);
        }
        if (lane == 0) {
#pragma unroll
            for (int w = 0; w < 9; w++) out[b * 9 + w] = acc[w];
        }
    }
}

extern "C" void kernel_launch(void* const* d_in, const int* in_sizes, int n_in,
                              void* d_out, int out_size) {
    const float* x  = (const float*)d_in[0];   // (32768, 9) fp32
    const float* wt = (const float*)d_in[1];   // (3, 9, 3) fp32
    float* out = (float*)d_out;                // (32768, 9) fp32
    int B = in_sizes[0] / 9;
    qsim_kernel<<<2048, 256>>>(x, wt, out, B);
}